// round 1
// baseline (speedup 1.0000x reference)
#include <cuda_runtime.h>

#define Bsz 64
#define Ssz 128
#define Fdim 16
#define Hdim 64

typedef unsigned long long u64;

__device__ __forceinline__ u64 pk(float a, float b) {
    u64 r; asm("mov.b64 %0, {%1,%2};" : "=l"(r) : "f"(a), "f"(b)); return r;
}
__device__ __forceinline__ u64 fma2(u64 a, u64 b, u64 c) {
    u64 d; asm("fma.rn.f32x2 %0, %1, %2, %3;" : "=l"(d) : "l"(a), "l"(b), "l"(c)); return d;
}
__device__ __forceinline__ float2 upk(u64 v) {
    float2 r; asm("mov.b64 {%0,%1}, %2;" : "=f"(r.x), "=f"(r.y) : "l"(v)); return r;
}

__device__ __forceinline__ float sigm(float x) { return __fdividef(1.f, 1.f + __expf(-x)); }
__device__ __forceinline__ float tanh_(float x) { return 1.f - __fdividef(2.f, __expf(2.f * x) + 1.f); }

// scratch: lstm outputs [branch][b][f][s][h], pooled [branch][b][f][h]
__device__ float g_lstm[2u * Bsz * Fdim * Ssz * Hdim];   // 16.7M floats
__device__ float g_pooled[2u * Bsz * Fdim * Hdim];

// ---------------------------------------------------------------------------
// LSTM: block = (bchunk of 16 batches, feature, branch). 128 blocks, 256 thr.
// Thread g owns gate g for 16 batches; Whh row lives in registers; h in smem.
// ---------------------------------------------------------------------------
__global__ __launch_bounds__(256) void lstm_kernel(
    const float* __restrict__ wd_x, const float* __restrict__ rd_x,
    const float* __restrict__ wd_Wih, const float* __restrict__ wd_Whh,
    const float* __restrict__ wd_bih, const float* __restrict__ wd_bhh,
    const float* __restrict__ rd_Wih, const float* __restrict__ rd_Whh,
    const float* __restrict__ rd_bih, const float* __restrict__ rd_bhh)
{
    int bc = blockIdx.x, f = blockIdx.y, br = blockIdx.z;
    int bBase = bc * 16;
    const float* x   = br ? rd_x   : wd_x;
    const float* Wih = br ? rd_Wih : wd_Wih;
    const float* Whh = br ? rd_Whh : wd_Whh;
    const float* bih = br ? rd_bih : wd_bih;
    const float* bhh = br ? rd_bhh : wd_bhh;

    __shared__ __align__(16) float h_s[64 * 16];
    __shared__ __align__(16) float c_s[64 * 16];
    __shared__ __align__(16) float gates_s[256 * 16];
    __shared__ __align__(16) float x_s[128 * 16];

    int tid = threadIdx.x;
    for (int i = tid; i < 128 * 16; i += 256) {
        int t = i >> 4, b = i & 15;
        x_s[i] = x[(size_t)(bBase + b) * Ssz * Fdim + t * Fdim + f];
    }
    for (int i = tid; i < 64 * 16; i += 256) { h_s[i] = 0.f; c_s[i] = 0.f; }

    int g = tid;
    float wih  = Wih[f * 256 + g];
    float bias = bih[f * 256 + g] + bhh[f * 256 + g];
    u64 wih2 = pk(wih, wih), bias2 = pk(bias, bias);

    float w[64];
#pragma unroll
    for (int j = 0; j < 64; j += 4) {
        float4 v = *(const float4*)&Whh[((size_t)f * 256 + g) * 64 + j];
        w[j] = v.x; w[j + 1] = v.y; w[j + 2] = v.z; w[j + 3] = v.w;
    }
    __syncthreads();

    for (int t = 0; t < Ssz; t++) {
        u64 acc[8];
        const u64* xp = (const u64*)&x_s[t * 16];
#pragma unroll
        for (int p = 0; p < 8; p++) acc[p] = fma2(wih2, xp[p], bias2);
#pragma unroll
        for (int j = 0; j < 64; j++) {
            u64 w2 = pk(w[j], w[j]);
            const ulonglong2* hp = (const ulonglong2*)&h_s[j * 16];
            ulonglong2 hA = hp[0], hB = hp[1], hC = hp[2], hD = hp[3];
            acc[0] = fma2(w2, hA.x, acc[0]); acc[1] = fma2(w2, hA.y, acc[1]);
            acc[2] = fma2(w2, hB.x, acc[2]); acc[3] = fma2(w2, hB.y, acc[3]);
            acc[4] = fma2(w2, hC.x, acc[4]); acc[5] = fma2(w2, hC.y, acc[5]);
            acc[6] = fma2(w2, hD.x, acc[6]); acc[7] = fma2(w2, hD.y, acc[7]);
        }
        ulonglong2* gp = (ulonglong2*)&gates_s[g * 16];
        gp[0] = make_ulonglong2(acc[0], acc[1]);
        gp[1] = make_ulonglong2(acc[2], acc[3]);
        gp[2] = make_ulonglong2(acc[4], acc[5]);
        gp[3] = make_ulonglong2(acc[6], acc[7]);
        __syncthreads();
        {
            int k = tid & 63, bg = tid >> 6;
            float4 iv = *(const float4*)&gates_s[k * 16 + bg * 4];
            float4 fv = *(const float4*)&gates_s[(64 + k) * 16 + bg * 4];
            float4 gv = *(const float4*)&gates_s[(128 + k) * 16 + bg * 4];
            float4 ov = *(const float4*)&gates_s[(192 + k) * 16 + bg * 4];
            float4 cv = *(const float4*)&c_s[k * 16 + bg * 4];
            float4 cn, hn;
            cn.x = sigm(fv.x) * cv.x + sigm(iv.x) * tanh_(gv.x); hn.x = sigm(ov.x) * tanh_(cn.x);
            cn.y = sigm(fv.y) * cv.y + sigm(iv.y) * tanh_(gv.y); hn.y = sigm(ov.y) * tanh_(cn.y);
            cn.z = sigm(fv.z) * cv.z + sigm(iv.z) * tanh_(gv.z); hn.z = sigm(ov.z) * tanh_(cn.z);
            cn.w = sigm(fv.w) * cv.w + sigm(iv.w) * tanh_(gv.w); hn.w = sigm(ov.w) * tanh_(cn.w);
            *(float4*)&c_s[k * 16 + bg * 4] = cn;
            *(float4*)&h_s[k * 16 + bg * 4] = hn;
            size_t gb = ((((size_t)br * Bsz + bBase + bg * 4) * Fdim + f) * Ssz + t) * Hdim + k;
            const size_t bs = (size_t)Fdim * Ssz * Hdim;
            g_lstm[gb] = hn.x; g_lstm[gb + bs] = hn.y;
            g_lstm[gb + 2 * bs] = hn.z; g_lstm[gb + 3 * bs] = hn.w;
        }
        __syncthreads();
    }
}

// ---------------------------------------------------------------------------
// Attention (fused): block = (f, b, branch) -> 2048 blocks, 256 threads.
// QKV in smem (transposed [g][s]); warp-per-q scores+softmax for both heads;
// writes mean attn weights directly to d_out; pooled via column-mean trick.
// ---------------------------------------------------------------------------
#define QS 132
#define ATTN_SMEM_FLOATS (12288 + 64 * QS + 192 * QS + 2048 + 256 + 64)

__global__ __launch_bounds__(256) void attn_kernel(
    const float* __restrict__ wd_aw, const float* __restrict__ wd_ab,
    const float* __restrict__ wd_ow, const float* __restrict__ wd_ob,
    const float* __restrict__ rd_aw, const float* __restrict__ rd_ab,
    const float* __restrict__ rd_ow, const float* __restrict__ rd_ob,
    float* __restrict__ d_out)
{
    int f = blockIdx.x, b = blockIdx.y, br = blockIdx.z;
    const float* aw = br ? rd_aw : wd_aw;
    const float* ab = br ? rd_ab : wd_ab;
    const float* ow = br ? rd_ow : wd_ow;
    const float* ob = br ? rd_ob : wd_ob;

    extern __shared__ float sm[];
    float* Win_s     = sm;                   // 192*64 = 12288
    float* xT        = Win_s + 12288;        // [64][QS]
    float* qkvT      = xT + 64 * QS;         // [192][QS]  (q rows 0-63, kT 64-127, v 128-191)
    float* wbar_part = qkvT + 192 * QS;      // [8 warps][2 heads][128]
    float* wbar_s    = wbar_part + 2048;     // [2][128]
    float* o_mean    = wbar_s + 256;         // [64]

    int tid = threadIdx.x;

    const float* wsrc = aw + (size_t)f * 192 * 64;
    for (int i = tid * 4; i < 12288; i += 1024)
        *(float4*)&Win_s[i] = *(const float4*)&wsrc[i];

    const float* xsrc = g_lstm + (((size_t)br * Bsz + b) * Fdim + f) * Ssz * Hdim;
    for (int i = tid * 4; i < Ssz * Hdim; i += 1024) {
        int s = i >> 6, h = i & 63;
        float4 v = *(const float4*)&xsrc[i];
        xT[(h + 0) * QS + s] = v.x; xT[(h + 1) * QS + s] = v.y;
        xT[(h + 2) * QS + s] = v.z; xT[(h + 3) * QS + s] = v.w;
    }
    __syncthreads();

    int lane = tid & 31, warp = tid >> 5;

    // QKV projection: warp <-> g stripe, lane <-> s-quad
    for (int g = warp; g < 192; g += 8) {
        float bb = ab[f * 192 + g];
        u64 a0 = pk(bb, bb), a1 = a0;
#pragma unroll
        for (int h = 0; h < 64; h++) {
            float wv = Win_s[g * 64 + h];
            u64 w2 = pk(wv, wv);
            ulonglong2 xv = *(const ulonglong2*)&xT[h * QS + lane * 4];
            a0 = fma2(w2, xv.x, a0);
            a1 = fma2(w2, xv.y, a1);
        }
        *(ulonglong2*)&qkvT[g * QS + lane * 4] = make_ulonglong2(a0, a1);
    }
    __syncthreads();

    const float scale = 0.17677669529663688f;  // 1/sqrt(32)
    float wbar_reg[8] = {0, 0, 0, 0, 0, 0, 0, 0};
    float* wout_base = d_out + 128 + (size_t)br * ((size_t)Fdim * Bsz * Ssz * Ssz)
                     + (((size_t)f * Bsz + b) * Ssz) * Ssz;

    for (int q = warp; q < Ssz; q += 8) {
        float wv[2][4];
#pragma unroll
        for (int n = 0; n < 2; n++) {
            u64 a0 = 0ull, a1 = 0ull;
#pragma unroll
            for (int d = 0; d < 32; d++) {
                int hg = n * 32 + d;
                float qv = qkvT[hg * QS + q];
                u64 q2 = pk(qv, qv);
                ulonglong2 kv = *(const ulonglong2*)&qkvT[(64 + hg) * QS + lane * 4];
                a0 = fma2(q2, kv.x, a0);
                a1 = fma2(q2, kv.y, a1);
            }
            float2 p0 = upk(a0), p1 = upk(a1);
            float s0 = p0.x * scale, s1 = p0.y * scale, s2 = p1.x * scale, s3 = p1.y * scale;
            float m = fmaxf(fmaxf(s0, s1), fmaxf(s2, s3));
#pragma unroll
            for (int off = 16; off > 0; off >>= 1)
                m = fmaxf(m, __shfl_xor_sync(0xffffffffu, m, off));
            float e0 = __expf(s0 - m), e1 = __expf(s1 - m);
            float e2 = __expf(s2 - m), e3 = __expf(s3 - m);
            float sum = e0 + e1 + e2 + e3;
#pragma unroll
            for (int off = 16; off > 0; off >>= 1)
                sum += __shfl_xor_sync(0xffffffffu, sum, off);
            float inv = __fdividef(1.f, sum);
            wv[n][0] = e0 * inv; wv[n][1] = e1 * inv;
            wv[n][2] = e2 * inv; wv[n][3] = e3 * inv;
            wbar_reg[n * 4 + 0] += wv[n][0]; wbar_reg[n * 4 + 1] += wv[n][1];
            wbar_reg[n * 4 + 2] += wv[n][2]; wbar_reg[n * 4 + 3] += wv[n][3];
        }
        float4 o4;
        o4.x = 0.5f * (wv[0][0] + wv[1][0]); o4.y = 0.5f * (wv[0][1] + wv[1][1]);
        o4.z = 0.5f * (wv[0][2] + wv[1][2]); o4.w = 0.5f * (wv[0][3] + wv[1][3]);
        *(float4*)&wout_base[(size_t)q * Ssz + lane * 4] = o4;
    }

    *(float4*)&wbar_part[(warp * 2 + 0) * 128 + lane * 4] =
        make_float4(wbar_reg[0], wbar_reg[1], wbar_reg[2], wbar_reg[3]);
    *(float4*)&wbar_part[(warp * 2 + 1) * 128 + lane * 4] =
        make_float4(wbar_reg[4], wbar_reg[5], wbar_reg[6], wbar_reg[7]);
    __syncthreads();

    {   // reduce column-means over warps; include 1/S
        int n = tid >> 7, k = tid & 127;
        float a = 0.f;
#pragma unroll
        for (int wpi = 0; wpi < 8; wpi++) a += wbar_part[(wpi * 2 + n) * 128 + k];
        wbar_s[n * 128 + k] = a * (1.f / 128.f);
    }
    __syncthreads();

    if (tid < 64) {  // o_mean[h] = sum_k wbar[head(h)][k] * v[k][h]
        int n = tid >> 5;
        float a = 0.f;
        for (int k = 0; k < 128; k++)
            a += wbar_s[n * 128 + k] * qkvT[(128 + tid) * QS + k];
        o_mean[tid] = a;
    }
    __syncthreads();

    if (tid < 64) {  // pooled = o_mean @ Wout^T + bout
        float a = ob[f * 64 + tid];
        const float* wrow = ow + ((size_t)f * 64 + tid) * 64;
        for (int h = 0; h < 64; h++) a += o_mean[h] * wrow[h];
        g_pooled[(((size_t)br * Bsz + b) * Fdim + f) * 64 + tid] = a;
    }
}

// ---------------------------------------------------------------------------
// Final: static DNN + time module + FC, one block per batch row.
// ---------------------------------------------------------------------------
__global__ __launch_bounds__(128) void final_kernel(
    const float* __restrict__ statin, const float* __restrict__ tg,
    const float* __restrict__ d1w, const float* __restrict__ d1b,
    const float* __restrict__ d2w, const float* __restrict__ d2b,
    const float* __restrict__ t1w, const float* __restrict__ t1b,
    const float* __restrict__ t2w, const float* __restrict__ t2b,
    const float* __restrict__ fcw, const float* __restrict__ fcb,
    float* __restrict__ out)
{
    __shared__ float s1[64], sf[32], t1v[16], tf[8], red[128];
    int b = blockIdx.x, tid = threadIdx.x;
    if (tid < 64) {
        float a = d1b[tid];
        for (int i = 0; i < 32; i++) a += statin[b * 32 + i] * d1w[tid * 32 + i];
        s1[tid] = fmaxf(a, 0.f);
    }
    if (tid < 16) t1v[tid] = fmaxf(t1b[tid] + tg[b] * t1w[tid], 0.f);
    __syncthreads();
    if (tid < 32) {
        float a = d2b[tid];
        for (int i = 0; i < 64; i++) a += s1[i] * d2w[tid * 64 + i];
        sf[tid] = fmaxf(a, 0.f);
    }
    if (tid < 8) {
        float a = t2b[tid];
        for (int i = 0; i < 16; i++) a += t1v[i] * t2w[tid * 16 + i];
        tf[tid] = fmaxf(a, 0.f);
    }
    __syncthreads();
    for (int o = 0; o < 2; o++) {
        float a = 0.f;
        for (int i = tid; i < 2088; i += 128) {
            float cv;
            if (i < 1024)      cv = g_pooled[(size_t)b * 1024 + i];
            else if (i < 2048) cv = g_pooled[(size_t)(Bsz + b) * 1024 + (i - 1024)];
            else if (i < 2080) cv = sf[i - 2048];
            else               cv = tf[i - 2080];
            a += cv * fcw[o * 2088 + i];
        }
        red[tid] = a;
        __syncthreads();
        for (int st = 64; st > 0; st >>= 1) {
            if (tid < st) red[tid] += red[tid + st];
            __syncthreads();
        }
        if (tid == 0) out[b * 2 + o] = red[0] + fcb[o];
        __syncthreads();
    }
}

extern "C" void kernel_launch(void* const* d_in, const int* in_sizes, int n_in,
                              void* d_out, int out_size)
{
    const float* wd_x    = (const float*)d_in[0];
    const float* rd_x    = (const float*)d_in[1];
    const float* statin  = (const float*)d_in[2];
    const float* tg      = (const float*)d_in[3];
    const float* wd_Wih  = (const float*)d_in[4];
    const float* wd_Whh  = (const float*)d_in[5];
    const float* wd_bih  = (const float*)d_in[6];
    const float* wd_bhh  = (const float*)d_in[7];
    const float* rd_Wih  = (const float*)d_in[8];
    const float* rd_Whh  = (const float*)d_in[9];
    const float* rd_bih  = (const float*)d_in[10];
    const float* rd_bhh  = (const float*)d_in[11];
    const float* wd_aw   = (const float*)d_in[12];
    const float* wd_ab   = (const float*)d_in[13];
    const float* wd_ow   = (const float*)d_in[14];
    const float* wd_ob   = (const float*)d_in[15];
    const float* rd_aw   = (const float*)d_in[16];
    const float* rd_ab   = (const float*)d_in[17];
    const float* rd_ow   = (const float*)d_in[18];
    const float* rd_ob   = (const float*)d_in[19];
    const float* d1w     = (const float*)d_in[20];
    const float* d1b     = (const float*)d_in[21];
    const float* d2w     = (const float*)d_in[22];
    const float* d2b     = (const float*)d_in[23];
    const float* t1w     = (const float*)d_in[24];
    const float* t1b     = (const float*)d_in[25];
    const float* t2w     = (const float*)d_in[26];
    const float* t2b     = (const float*)d_in[27];
    const float* fcw     = (const float*)d_in[28];
    const float* fcb     = (const float*)d_in[29];
    float* out = (float*)d_out;

    cudaFuncSetAttribute(attn_kernel, cudaFuncAttributeMaxDynamicSharedMemorySize,
                         ATTN_SMEM_FLOATS * 4);

    lstm_kernel<<<dim3(4, Fdim, 2), 256>>>(
        wd_x, rd_x, wd_Wih, wd_Whh, wd_bih, wd_bhh, rd_Wih, rd_Whh, rd_bih, rd_bhh);

    attn_kernel<<<dim3(Fdim, Bsz, 2), 256, ATTN_SMEM_FLOATS * 4>>>(
        wd_aw, wd_ab, wd_ow, wd_ob, rd_aw, rd_ab, rd_ow, rd_ob, out);

    final_kernel<<<Bsz, 128>>>(
        statin, tg, d1w, d1b, d2w, d2b, t1w, t1b, t2w, t2b, fcw, fcb, out);
}